// round 11
// baseline (speedup 1.0000x reference)
#include <cuda_runtime.h>
#include <cuda_fp16.h>
#include <cstdint>

#define N_NODES 100000
#define DIM 64
#define N_EDGES 1600000
#define MAXDEG 64
#define GATHER_BLOCKS 1184

#define GEMM_BLOCKS ((N_NODES + 127) / 128)        // 782
#define BUCKET_BLOCKS ((N_EDGES + 255) / 256)      // 6250
#define FUSED_BLOCKS (GEMM_BLOCKS + BUCKET_BLOCKS) // 7032

// Scratch (__device__ globals; zero-initialized at load).
// g_cnt is reset to 0 by gather_reduce_kernel after each use, so every
// kernel_launch call sees zeros (first call: static zero-init).
__device__ uint4 g_y_h4[(size_t)N_NODES * DIM / 8];   // y = x@W1, fp16 rows (128B)
__device__ int   g_cnt[N_NODES];                      // per-dst degree
__device__ int   g_slots[(size_t)N_NODES * MAXDEG];   // BYTE offsets (src<<7) per dst

// ---------------------------------------------------------------------------
// Kernel 1 (fused, grid-union): blocks [0,GEMM_BLOCKS) run the R9-proven
// HMMA gemm (y = x@W1 -> fp16); blocks [GEMM_BLOCKS, FUSED_BLOCKS) run the
// lean edge bucket.  The two halves are data-independent (g_cnt was reset
// by the previous gather), so they overlap on the SMs.
// ---------------------------------------------------------------------------
__global__ void __launch_bounds__(256) fused_gemm_bucket_kernel(
        const float* __restrict__ x, const float* __restrict__ W1,
        const void* __restrict__ eptr, float* __restrict__ out) {
    int bid = blockIdx.x;
    int t = threadIdx.x;

    if (bid < GEMM_BLOCKS) {
        // ================= GEMM branch (R9-exact) =================
        __shared__ __half xs[128][72];
        __shared__ __half wt[64][72];

        // ---- stage W1 transposed: wt[n][k] = W1[k][n] ----
        {
            int n = t >> 2, kk = (t & 3) * 16;
            #pragma unroll
            for (int q = 0; q < 16; q += 2) {
                float w0 = __ldg(&W1[(kk + q) * DIM + n]);
                float w1 = __ldg(&W1[(kk + q + 1) * DIM + n]);
                *(__half2*)&wt[n][kk + q] = __floats2half2_rn(w0, w1);
            }
        }

        // ---- stage x tile (fp32 -> fp16), coalesced float4 loads ----
        int m0 = bid * 128;
        {
            int row = t >> 1, half = t & 1;
            int node = m0 + row;
            if (node < N_NODES) {
                const float4* src = (const float4*)(x + (size_t)node * DIM + half * 32);
                #pragma unroll
                for (int q = 0; q < 8; q++) {
                    float4 v = __ldg(&src[q]);
                    *(__half2*)&xs[row][half * 32 + q * 4]     = __floats2half2_rn(v.x, v.y);
                    *(__half2*)&xs[row][half * 32 + q * 4 + 2] = __floats2half2_rn(v.z, v.w);
                }
            } else {
                #pragma unroll
                for (int q = 0; q < 16; q++)
                    *(__half2*)&xs[row][half * 32 + q * 2] = __half2half2(__ushort_as_half(0));
            }
        }
        __syncthreads();

        // ---- mma mainloop ----
        int w = t >> 5, lane = t & 31;
        int r = lane >> 2, c = lane & 3;
        int mrow = 16 * w + r;

        float C[8][4];
        #pragma unroll
        for (int nt = 0; nt < 8; nt++)
            #pragma unroll
            for (int q = 0; q < 4; q++) C[nt][q] = 0.f;

        #pragma unroll
        for (int ks = 0; ks < 4; ks++) {
            int k0 = ks * 16;
            unsigned a0 = *(const unsigned*)&xs[mrow][k0 + c * 2];
            unsigned a1 = *(const unsigned*)&xs[mrow + 8][k0 + c * 2];
            unsigned a2 = *(const unsigned*)&xs[mrow][k0 + c * 2 + 8];
            unsigned a3 = *(const unsigned*)&xs[mrow + 8][k0 + c * 2 + 8];
            #pragma unroll
            for (int nt = 0; nt < 8; nt++) {
                unsigned b0 = *(const unsigned*)&wt[nt * 8 + r][k0 + c * 2];
                unsigned b1 = *(const unsigned*)&wt[nt * 8 + r][k0 + c * 2 + 8];
                asm("mma.sync.aligned.m16n8k16.row.col.f32.f16.f16.f32 "
                    "{%0,%1,%2,%3}, {%4,%5,%6,%7}, {%8,%9}, {%0,%1,%2,%3};"
                    : "+f"(C[nt][0]), "+f"(C[nt][1]), "+f"(C[nt][2]), "+f"(C[nt][3])
                    : "r"(a0), "r"(a1), "r"(a2), "r"(a3), "r"(b0), "r"(b1));
            }
        }

        // ---- store C -> g_y (fp16) ----
        int node0 = m0 + mrow;
        char* ybase = (char*)g_y_h4;
        #pragma unroll
        for (int nt = 0; nt < 8; nt++) {
            __half2 h0 = __floats2half2_rn(C[nt][0], C[nt][1]);
            __half2 h1 = __floats2half2_rn(C[nt][2], C[nt][3]);
            int colb = (nt * 8 + c * 2) * 2;
            if (node0 < N_NODES)
                *(unsigned*)(ybase + (size_t)node0 * 128 + colb) = *(unsigned*)&h0;
            if (node0 + 8 < N_NODES)
                *(unsigned*)(ybase + (size_t)(node0 + 8) * 128 + colb) = *(unsigned*)&h1;
        }
    } else {
        // ================= Bucket branch (lean) =================
        if (bid == GEMM_BLOCKS && t < DIM) out[t] = 0.0f;

        const unsigned* w = (const unsigned*)eptr;
        unsigned o = w[1] | w[3] | w[5] | w[7] | w[9] | w[11] | w[13] | w[15];
        bool is64 = (o == 0);   // int64 little-endian: odd words = zero high halves

        int e = (bid - GEMM_BLOCKS) * 256 + t;
        if (e >= N_EDGES) return;
        int s, d;
        if (is64) {
            const long long* ei = (const long long*)eptr;
            s = (int)__ldg(&ei[e]);
            d = (int)__ldg(&ei[N_EDGES + e]);
        } else {
            const int* ei = (const int*)eptr;
            s = __ldg(&ei[e]);
            d = __ldg(&ei[N_EDGES + e]);
        }
        int pos = atomicAdd(&g_cnt[d], 1);
        if (pos < MAXDEG) g_slots[(size_t)d * MAXDEG + pos] = s << 7;  // byte offset
    }
}

// ---------------------------------------------------------------------------
// Kernel 2: fused gather + epilogue + per-block W2 GEMV into out.
// One warp per node; fp16 HADD2 accumulation; pre-scaled byte offsets.
// Resets g_cnt[i] to 0 after reading it (warp-lockstep: reads precede the
// store), keeping every kernel_launch call's work identical.
// ---------------------------------------------------------------------------
__global__ void __launch_bounds__(256) gather_reduce_kernel(
        const float* __restrict__ wts, const float* __restrict__ b1,
        const float* __restrict__ W2, const float* __restrict__ b2,
        float* __restrict__ out) {
    int lane = threadIdx.x & 31;
    int warp = threadIdx.x >> 5;
    float2 b = ((const float2*)b1)[lane];

    const char* ylane = (const char*)g_y_h4 + lane * 4;  // per-lane column base

    float2 accS = make_float2(0.f, 0.f);
    float accw = 0.f;

    int gw = blockIdx.x * 8 + warp;
    int nw = GATHER_BLOCKS * 8;
    for (int i = gw; i < N_NODES; i += nw) {
        int cnt = g_cnt[i];
        if (cnt > MAXDEG) cnt = MAXDEG;
        const int* slots = g_slots + (size_t)i * MAXDEG;
        int s0 = (lane < cnt) ? __ldg(&slots[lane]) : 0;
        int s1 = (lane + 32 < cnt) ? __ldg(&slots[lane + 32]) : 0;
        if (lane == 0) g_cnt[i] = 0;          // reset for next call

        unsigned hs = *(const unsigned*)(ylane + ((size_t)(unsigned)i << 7));
        __half2 acc0 = *(const __half2*)&hs;
        __half2 acc1 = __half2half2(__ushort_as_half(0));

        int c0 = cnt < 32 ? cnt : 32;
        int j = 0;
        for (; j + 4 <= c0; j += 4) {
            int oa = __shfl_sync(0xffffffffu, s0, j + 0);
            int ob = __shfl_sync(0xffffffffu, s0, j + 1);
            int oc = __shfl_sync(0xffffffffu, s0, j + 2);
            int od = __shfl_sync(0xffffffffu, s0, j + 3);
            unsigned ha = *(const unsigned*)(ylane + (size_t)(unsigned)oa);
            unsigned hb = *(const unsigned*)(ylane + (size_t)(unsigned)ob);
            unsigned hc = *(const unsigned*)(ylane + (size_t)(unsigned)oc);
            unsigned hd = *(const unsigned*)(ylane + (size_t)(unsigned)od);
            acc0 = __hadd2(acc0, __hadd2(*(const __half2*)&ha, *(const __half2*)&hb));
            acc1 = __hadd2(acc1, __hadd2(*(const __half2*)&hc, *(const __half2*)&hd));
        }
        for (; j < c0; j++) {
            int oa = __shfl_sync(0xffffffffu, s0, j);
            unsigned ha = *(const unsigned*)(ylane + (size_t)(unsigned)oa);
            acc0 = __hadd2(acc0, *(const __half2*)&ha);
        }
        for (j = 32; j < cnt; j++) {
            int oa = __shfl_sync(0xffffffffu, s1, j - 32);
            unsigned ha = *(const unsigned*)(ylane + (size_t)(unsigned)oa);
            acc1 = __hadd2(acc1, *(const __half2*)&ha);
        }

        float2 f = __half22float2(__hadd2(acc0, acc1));
        float wv = __ldg(&wts[i]);
        float z0 = fmaxf(f.x + b.x, 0.f);
        float z1 = fmaxf(f.y + b.y, 0.f);
        accS.x = fmaf(wv, z0, accS.x);
        accS.y = fmaf(wv, z1, accS.y);
        if (lane == 0) accw += wv;
    }

    // ---- block reduction of partial S ----
    __shared__ float sS[DIM];
    __shared__ float sw;
    __shared__ float sP[256];
    if (threadIdx.x < DIM) sS[threadIdx.x] = 0.f;
    if (threadIdx.x == 0) sw = 0.f;
    __syncthreads();
    atomicAdd(&sS[lane * 2 + 0], accS.x);
    atomicAdd(&sS[lane * 2 + 1], accS.y);
    if (lane == 0) atomicAdd(&sw, accw);
    __syncthreads();

    // ---- apply W2 to block partial: out += sS @ W2 + sw * b2 ----
    {
        int jj = threadIdx.x & 63;
        int kq = threadIdx.x >> 6;
        float acc = 0.f;
        #pragma unroll
        for (int q = 0; q < 16; q++) {
            int k = kq * 16 + q;
            acc = fmaf(sS[k], __ldg(&W2[k * DIM + jj]), acc);
        }
        if (kq == 0) acc = fmaf(sw, __ldg(&b2[jj]), acc);
        sP[threadIdx.x] = acc;
        __syncthreads();
        if (threadIdx.x < DIM)
            atomicAdd(&out[jj], sP[jj] + sP[64 + jj] + sP[128 + jj] + sP[192 + jj]);
    }
}

// ---------------------------------------------------------------------------
extern "C" void kernel_launch(void* const* d_in, const int* in_sizes, int n_in,
                              void* d_out, int out_size) {
    const float* x   = (const float*)d_in[0];
    const void*  ei  = d_in[1];
    const float* wts = (const float*)d_in[2];
    const float* W1  = (const float*)d_in[3];
    const float* b1  = (const float*)d_in[4];
    const float* W2  = (const float*)d_in[5];
    const float* b2  = (const float*)d_in[6];
    float* out = (float*)d_out;

    fused_gemm_bucket_kernel<<<FUSED_BLOCKS, 256>>>(x, W1, ei, out);
    gather_reduce_kernel<<<GATHER_BLOCKS, 256>>>(wts, b1, W2, b2, out);
}

// round 13
// speedup vs baseline: 2.7768x; 2.7768x over previous
#include <cuda_runtime.h>
#include <cuda_fp16.h>
#include <cstdint>

#define N_NODES 100000
#define DIM 64
#define N_EDGES 1600000
#define MAXDEG 64
#define GATHER_BLOCKS 1184

#define GEMM_BLOCKS ((N_NODES + 127) / 128)        // 782
#define BUCKET_BLOCKS ((N_EDGES + 255) / 256)      // 6250
#define FUSED_BLOCKS (GEMM_BLOCKS + BUCKET_BLOCKS) // 7032

// Scratch (__device__ globals; zero-initialized at load).
__device__ uint4 g_y_h4[(size_t)N_NODES * DIM / 8];   // y = x@W1, fp16 rows (128B)
__device__ int   g_cnt[N_NODES];                      // per-dst degree
__device__ int   g_slots[(size_t)N_NODES * MAXDEG];   // BYTE offsets (src<<7) per dst

// ---------------------------------------------------------------------------
// Kernel 0: zero g_cnt (vectorized) + out[64].  Separate launch so the reset
// can never race with readers (the R12 bug) — all ordering via launch order.
// ---------------------------------------------------------------------------
__global__ void zero_kernel(float* __restrict__ out) {
    int i = blockIdx.x * blockDim.x + threadIdx.x;
    if (i < N_NODES / 4) ((uint4*)g_cnt)[i] = make_uint4(0, 0, 0, 0);
    if (i < DIM) out[i] = 0.0f;
}

// ---------------------------------------------------------------------------
// Kernel 1 (fused, grid-union; R11-measured ~21us): blocks [0,GEMM_BLOCKS)
// run the HMMA gemm (y = x@W1 -> fp16); blocks [GEMM_BLOCKS, FUSED_BLOCKS)
// run the lean edge bucket.  Data-independent halves overlap on the SMs.
// ---------------------------------------------------------------------------
__global__ void __launch_bounds__(256) fused_gemm_bucket_kernel(
        const float* __restrict__ x, const float* __restrict__ W1,
        const void* __restrict__ eptr) {
    int bid = blockIdx.x;
    int t = threadIdx.x;

    if (bid < GEMM_BLOCKS) {
        // ================= GEMM branch =================
        __shared__ __half xs[128][72];
        __shared__ __half wt[64][72];

        // ---- stage W1 transposed: wt[n][k] = W1[k][n] ----
        {
            int n = t >> 2, kk = (t & 3) * 16;
            #pragma unroll
            for (int q = 0; q < 16; q += 2) {
                float w0 = __ldg(&W1[(kk + q) * DIM + n]);
                float w1 = __ldg(&W1[(kk + q + 1) * DIM + n]);
                *(__half2*)&wt[n][kk + q] = __floats2half2_rn(w0, w1);
            }
        }

        // ---- stage x tile (fp32 -> fp16), coalesced float4 loads ----
        int m0 = bid * 128;
        {
            int row = t >> 1, half = t & 1;
            int node = m0 + row;
            if (node < N_NODES) {
                const float4* src = (const float4*)(x + (size_t)node * DIM + half * 32);
                #pragma unroll
                for (int q = 0; q < 8; q++) {
                    float4 v = __ldg(&src[q]);
                    *(__half2*)&xs[row][half * 32 + q * 4]     = __floats2half2_rn(v.x, v.y);
                    *(__half2*)&xs[row][half * 32 + q * 4 + 2] = __floats2half2_rn(v.z, v.w);
                }
            } else {
                #pragma unroll
                for (int q = 0; q < 16; q++)
                    *(__half2*)&xs[row][half * 32 + q * 2] = __half2half2(__ushort_as_half(0));
            }
        }
        __syncthreads();

        // ---- mma mainloop ----
        int w = t >> 5, lane = t & 31;
        int r = lane >> 2, c = lane & 3;
        int mrow = 16 * w + r;

        float C[8][4];
        #pragma unroll
        for (int nt = 0; nt < 8; nt++)
            #pragma unroll
            for (int q = 0; q < 4; q++) C[nt][q] = 0.f;

        #pragma unroll
        for (int ks = 0; ks < 4; ks++) {
            int k0 = ks * 16;
            unsigned a0 = *(const unsigned*)&xs[mrow][k0 + c * 2];
            unsigned a1 = *(const unsigned*)&xs[mrow + 8][k0 + c * 2];
            unsigned a2 = *(const unsigned*)&xs[mrow][k0 + c * 2 + 8];
            unsigned a3 = *(const unsigned*)&xs[mrow + 8][k0 + c * 2 + 8];
            #pragma unroll
            for (int nt = 0; nt < 8; nt++) {
                unsigned b0 = *(const unsigned*)&wt[nt * 8 + r][k0 + c * 2];
                unsigned b1 = *(const unsigned*)&wt[nt * 8 + r][k0 + c * 2 + 8];
                asm("mma.sync.aligned.m16n8k16.row.col.f32.f16.f16.f32 "
                    "{%0,%1,%2,%3}, {%4,%5,%6,%7}, {%8,%9}, {%0,%1,%2,%3};"
                    : "+f"(C[nt][0]), "+f"(C[nt][1]), "+f"(C[nt][2]), "+f"(C[nt][3])
                    : "r"(a0), "r"(a1), "r"(a2), "r"(a3), "r"(b0), "r"(b1));
            }
        }

        // ---- store C -> g_y (fp16) ----
        int node0 = m0 + mrow;
        char* ybase = (char*)g_y_h4;
        #pragma unroll
        for (int nt = 0; nt < 8; nt++) {
            __half2 h0 = __floats2half2_rn(C[nt][0], C[nt][1]);
            __half2 h1 = __floats2half2_rn(C[nt][2], C[nt][3]);
            int colb = (nt * 8 + c * 2) * 2;
            if (node0 < N_NODES)
                *(unsigned*)(ybase + (size_t)node0 * 128 + colb) = *(unsigned*)&h0;
            if (node0 + 8 < N_NODES)
                *(unsigned*)(ybase + (size_t)(node0 + 8) * 128 + colb) = *(unsigned*)&h1;
        }
    } else {
        // ================= Bucket branch (lean) =================
        const unsigned* w = (const unsigned*)eptr;
        unsigned o = w[1] | w[3] | w[5] | w[7] | w[9] | w[11] | w[13] | w[15];
        bool is64 = (o == 0);   // int64 little-endian: odd words = zero high halves

        int e = (bid - GEMM_BLOCKS) * 256 + t;
        if (e >= N_EDGES) return;
        int s, d;
        if (is64) {
            const long long* ei = (const long long*)eptr;
            s = (int)__ldg(&ei[e]);
            d = (int)__ldg(&ei[N_EDGES + e]);
        } else {
            const int* ei = (const int*)eptr;
            s = __ldg(&ei[e]);
            d = __ldg(&ei[N_EDGES + e]);
        }
        int pos = atomicAdd(&g_cnt[d], 1);
        if (pos < MAXDEG) g_slots[(size_t)d * MAXDEG + pos] = s << 7;  // byte offset
    }
}

// ---------------------------------------------------------------------------
// Kernel 2: fused gather + epilogue + per-block W2 GEMV into out.
// Hot loop = R8-measured 30.4us form.  NO state resets anywhere (the R12
// lesson): g_cnt is zeroed by next call's zero_kernel.
// ---------------------------------------------------------------------------
__global__ void __launch_bounds__(256) gather_reduce_kernel(
        const float* __restrict__ wts, const float* __restrict__ b1,
        const float* __restrict__ W2, const float* __restrict__ b2,
        float* __restrict__ out) {
    int lane = threadIdx.x & 31;
    int warp = threadIdx.x >> 5;
    float2 b = ((const float2*)b1)[lane];

    const char* ylane = (const char*)g_y_h4 + lane * 4;  // per-lane column base

    float2 accS = make_float2(0.f, 0.f);
    float accw = 0.f;

    int gw = blockIdx.x * 8 + warp;
    int nw = GATHER_BLOCKS * 8;
    for (int i = gw; i < N_NODES; i += nw) {
        int cnt = g_cnt[i];
        if (cnt > MAXDEG) cnt = MAXDEG;
        const int* slots = g_slots + (size_t)i * MAXDEG;
        int s0 = (lane < cnt) ? __ldg(&slots[lane]) : 0;
        int s1 = (lane + 32 < cnt) ? __ldg(&slots[lane + 32]) : 0;

        unsigned hs = *(const unsigned*)(ylane + ((size_t)(unsigned)i << 7));
        __half2 acc0 = *(const __half2*)&hs;
        __half2 acc1 = __half2half2(__ushort_as_half(0));

        int c0 = cnt < 32 ? cnt : 32;
        int j = 0;
        for (; j + 4 <= c0; j += 4) {
            int oa = __shfl_sync(0xffffffffu, s0, j + 0);
            int ob = __shfl_sync(0xffffffffu, s0, j + 1);
            int oc = __shfl_sync(0xffffffffu, s0, j + 2);
            int od = __shfl_sync(0xffffffffu, s0, j + 3);
            unsigned ha = *(const unsigned*)(ylane + (size_t)(unsigned)oa);
            unsigned hb = *(const unsigned*)(ylane + (size_t)(unsigned)ob);
            unsigned hc = *(const unsigned*)(ylane + (size_t)(unsigned)oc);
            unsigned hd = *(const unsigned*)(ylane + (size_t)(unsigned)od);
            acc0 = __hadd2(acc0, __hadd2(*(const __half2*)&ha, *(const __half2*)&hb));
            acc1 = __hadd2(acc1, __hadd2(*(const __half2*)&hc, *(const __half2*)&hd));
        }
        for (; j < c0; j++) {
            int oa = __shfl_sync(0xffffffffu, s0, j);
            unsigned ha = *(const unsigned*)(ylane + (size_t)(unsigned)oa);
            acc0 = __hadd2(acc0, *(const __half2*)&ha);
        }
        for (j = 32; j < cnt; j++) {
            int oa = __shfl_sync(0xffffffffu, s1, j - 32);
            unsigned ha = *(const unsigned*)(ylane + (size_t)(unsigned)oa);
            acc1 = __hadd2(acc1, *(const __half2*)&ha);
        }

        float2 f = __half22float2(__hadd2(acc0, acc1));
        float wv = __ldg(&wts[i]);
        float z0 = fmaxf(f.x + b.x, 0.f);
        float z1 = fmaxf(f.y + b.y, 0.f);
        accS.x = fmaf(wv, z0, accS.x);
        accS.y = fmaf(wv, z1, accS.y);
        if (lane == 0) accw += wv;
    }

    // ---- block reduction of partial S ----
    __shared__ float sS[DIM];
    __shared__ float sw;
    __shared__ float sP[256];
    if (threadIdx.x < DIM) sS[threadIdx.x] = 0.f;
    if (threadIdx.x == 0) sw = 0.f;
    __syncthreads();
    atomicAdd(&sS[lane * 2 + 0], accS.x);
    atomicAdd(&sS[lane * 2 + 1], accS.y);
    if (lane == 0) atomicAdd(&sw, accw);
    __syncthreads();

    // ---- apply W2 to block partial: out += sS @ W2 + sw * b2 ----
    {
        int jj = threadIdx.x & 63;
        int kq = threadIdx.x >> 6;
        float acc = 0.f;
        #pragma unroll
        for (int q = 0; q < 16; q++) {
            int k = kq * 16 + q;
            acc = fmaf(sS[k], __ldg(&W2[k * DIM + jj]), acc);
        }
        if (kq == 0) acc = fmaf(sw, __ldg(&b2[jj]), acc);
        sP[threadIdx.x] = acc;
        __syncthreads();
        if (threadIdx.x < DIM)
            atomicAdd(&out[jj], sP[jj] + sP[64 + jj] + sP[128 + jj] + sP[192 + jj]);
    }
}

// ---------------------------------------------------------------------------
extern "C" void kernel_launch(void* const* d_in, const int* in_sizes, int n_in,
                              void* d_out, int out_size) {
    const float* x   = (const float*)d_in[0];
    const void*  ei  = d_in[1];
    const float* wts = (const float*)d_in[2];
    const float* W1  = (const float*)d_in[3];
    const float* b1  = (const float*)d_in[4];
    const float* W2  = (const float*)d_in[5];
    const float* b2  = (const float*)d_in[6];
    float* out = (float*)d_out;

    zero_kernel<<<98, 256>>>(out);
    fused_gemm_bucket_kernel<<<FUSED_BLOCKS, 256>>>(x, W1, ei);
    gather_reduce_kernel<<<GATHER_BLOCKS, 256>>>(wts, b1, W2, b2, out);
}

// round 14
// speedup vs baseline: 2.9174x; 1.0506x over previous
#include <cuda_runtime.h>
#include <cuda_fp16.h>
#include <cstdint>

#define N_NODES 100000
#define DIM 64
#define N_EDGES 1600000
#define MAXDEG 64
#define GATHER_BLOCKS 1184

#define GEMM_BLOCKS ((N_NODES + 127) / 128)        // 782
#define BUCKET_BLOCKS ((N_EDGES + 255) / 256)      // 6250
#define FUSED_BLOCKS (GEMM_BLOCKS + BUCKET_BLOCKS) // 7032

// Scratch (__device__ globals; zero-initialized at load).
__device__ uint4  g_y_h4[(size_t)N_NODES * DIM / 8];  // y = x@W1, fp16 rows (128B)
__device__ int    g_cnt[N_NODES];                     // per-dst degree
__device__ int    g_slots[(size_t)N_NODES * MAXDEG];  // BYTE offsets (src<<7) per dst
__device__ __half g_w1t[DIM * DIM];                   // W1 transposed, fp16: [n][k]

// ---------------------------------------------------------------------------
// Kernel 0: zero g_cnt + out[64]; block 98 builds g_w1t[n][k] = W1[k][n] fp16
// (once per call, so gemm blocks can stage W1 with coalesced loads).
// ---------------------------------------------------------------------------
__global__ void zero_kernel(float* __restrict__ out, const float* __restrict__ W1) {
    if (blockIdx.x == 98) {
        for (int idx = threadIdx.x; idx < DIM * DIM; idx += 256) {
            int k = idx >> 6, n = idx & 63;
            g_w1t[n * DIM + k] = __float2half_rn(W1[idx]);
        }
        return;
    }
    int i = blockIdx.x * 256 + threadIdx.x;
    if (i < N_NODES / 4) ((uint4*)g_cnt)[i] = make_uint4(0, 0, 0, 0);
    if (i < DIM) out[i] = 0.0f;
}

// ---------------------------------------------------------------------------
// Kernel 1 (fused grid-union): blocks [0,GEMM_BLOCKS) = HMMA gemm with
// wavefront-clean staging; blocks [GEMM_BLOCKS,FUSED_BLOCKS) = lean bucket.
// ---------------------------------------------------------------------------
__global__ void __launch_bounds__(256) fused_gemm_bucket_kernel(
        const float* __restrict__ x, const void* __restrict__ eptr) {
    int bid = blockIdx.x;
    int t = threadIdx.x;

    if (bid < GEMM_BLOCKS) {
        // ================= GEMM branch =================
        __shared__ __half xs[128][72];
        __shared__ __half wt[64][72];

        // ---- stage W1t: 8KB coalesced (2 x uint4 per thread) ----
        {
            const uint4* src = (const uint4*)g_w1t;     // 512 uint4
            #pragma unroll
            for (int p = 0; p < 2; p++) {
                int idx = t + p * 256;
                uint4 v = src[idx];                     // 8 halfs, row n=idx>>3
                *(uint4*)&wt[idx >> 3][(idx & 7) * 8] = v;
            }
        }

        // ---- stage x tile: LINEAR read of the contiguous 32KB tile ----
        int m0 = bid * 128;
        {
            const char* xb = (const char*)x;
            size_t tile_byte = (size_t)m0 * 256;
            size_t xlimit = (size_t)N_NODES * 256;
            #pragma unroll
            for (int p = 0; p < 8; p++) {
                int off = t * 16 + p * 4096;            // byte within tile
                float4 v = make_float4(0.f, 0.f, 0.f, 0.f);
                if (tile_byte + off < xlimit)
                    v = *(const float4*)(xb + tile_byte + off);
                int row = off >> 8;                     // 256B per x row
                int colh = (off & 255) >> 2;            // half-col index
                *(__half2*)&xs[row][colh]     = __floats2half2_rn(v.x, v.y);
                *(__half2*)&xs[row][colh + 2] = __floats2half2_rn(v.z, v.w);
            }
        }
        __syncthreads();

        // ---- mma mainloop (unchanged: same xs/wt layout) ----
        int w = t >> 5, lane = t & 31;
        int r = lane >> 2, c = lane & 3;
        int mrow = 16 * w + r;

        float C[8][4];
        #pragma unroll
        for (int nt = 0; nt < 8; nt++)
            #pragma unroll
            for (int q = 0; q < 4; q++) C[nt][q] = 0.f;

        #pragma unroll
        for (int ks = 0; ks < 4; ks++) {
            int k0 = ks * 16;
            unsigned a0 = *(const unsigned*)&xs[mrow][k0 + c * 2];
            unsigned a1 = *(const unsigned*)&xs[mrow + 8][k0 + c * 2];
            unsigned a2 = *(const unsigned*)&xs[mrow][k0 + c * 2 + 8];
            unsigned a3 = *(const unsigned*)&xs[mrow + 8][k0 + c * 2 + 8];
            #pragma unroll
            for (int nt = 0; nt < 8; nt++) {
                unsigned b0 = *(const unsigned*)&wt[nt * 8 + r][k0 + c * 2];
                unsigned b1 = *(const unsigned*)&wt[nt * 8 + r][k0 + c * 2 + 8];
                asm("mma.sync.aligned.m16n8k16.row.col.f32.f16.f16.f32 "
                    "{%0,%1,%2,%3}, {%4,%5,%6,%7}, {%8,%9}, {%0,%1,%2,%3};"
                    : "+f"(C[nt][0]), "+f"(C[nt][1]), "+f"(C[nt][2]), "+f"(C[nt][3])
                    : "r"(a0), "r"(a1), "r"(a2), "r"(a3), "r"(b0), "r"(b1));
            }
        }

        // ---- C -> smem (conflict-free STS), then LINEAR coalesced STG ----
        __syncthreads();                    // xs reads done; reuse as C tile
        #pragma unroll
        for (int nt = 0; nt < 8; nt++) {
            int coln = nt * 8 + c * 2;
            *(__half2*)&xs[mrow][coln]     = __floats2half2_rn(C[nt][0], C[nt][1]);
            *(__half2*)&xs[mrow + 8][coln] = __floats2half2_rn(C[nt][2], C[nt][3]);
        }
        __syncthreads();
        {
            char* yb = (char*)g_y_h4;
            size_t ybyte0 = (size_t)m0 * 128;
            size_t ylimit = (size_t)N_NODES * 128;
            #pragma unroll
            for (int p = 0; p < 4; p++) {
                int off = t * 16 + p * 4096;            // byte within y tile
                int row = off >> 7;                     // 128B per y row
                int colh = (off & 127) >> 1;            // half-col index
                uint4 v = *(uint4*)&xs[row][colh];
                if (ybyte0 + off < ylimit)
                    *(uint4*)(yb + ybyte0 + off) = v;
            }
        }
    } else {
        // ================= Bucket branch (lean, R13-exact) =================
        const unsigned* w = (const unsigned*)eptr;
        unsigned o = w[1] | w[3] | w[5] | w[7] | w[9] | w[11] | w[13] | w[15];
        bool is64 = (o == 0);   // int64 little-endian: odd words = zero high halves

        int e = (bid - GEMM_BLOCKS) * 256 + t;
        if (e >= N_EDGES) return;
        int s, d;
        if (is64) {
            const long long* ei = (const long long*)eptr;
            s = (int)__ldg(&ei[e]);
            d = (int)__ldg(&ei[N_EDGES + e]);
        } else {
            const int* ei = (const int*)eptr;
            s = __ldg(&ei[e]);
            d = __ldg(&ei[N_EDGES + e]);
        }
        int pos = atomicAdd(&g_cnt[d], 1);
        if (pos < MAXDEG) g_slots[(size_t)d * MAXDEG + pos] = s << 7;  // byte offset
    }
}

// ---------------------------------------------------------------------------
// Kernel 2: fused gather + epilogue + per-block W2 GEMV into out (R13-exact).
// ---------------------------------------------------------------------------
__global__ void __launch_bounds__(256) gather_reduce_kernel(
        const float* __restrict__ wts, const float* __restrict__ b1,
        const float* __restrict__ W2, const float* __restrict__ b2,
        float* __restrict__ out) {
    int lane = threadIdx.x & 31;
    int warp = threadIdx.x >> 5;
    float2 b = ((const float2*)b1)[lane];

    const char* ylane = (const char*)g_y_h4 + lane * 4;  // per-lane column base

    float2 accS = make_float2(0.f, 0.f);
    float accw = 0.f;

    int gw = blockIdx.x * 8 + warp;
    int nw = GATHER_BLOCKS * 8;
    for (int i = gw; i < N_NODES; i += nw) {
        int cnt = g_cnt[i];
        if (cnt > MAXDEG) cnt = MAXDEG;
        const int* slots = g_slots + (size_t)i * MAXDEG;
        int s0 = (lane < cnt) ? __ldg(&slots[lane]) : 0;
        int s1 = (lane + 32 < cnt) ? __ldg(&slots[lane + 32]) : 0;

        unsigned hs = *(const unsigned*)(ylane + ((size_t)(unsigned)i << 7));
        __half2 acc0 = *(const __half2*)&hs;
        __half2 acc1 = __half2half2(__ushort_as_half(0));

        int c0 = cnt < 32 ? cnt : 32;
        int j = 0;
        for (; j + 4 <= c0; j += 4) {
            int oa = __shfl_sync(0xffffffffu, s0, j + 0);
            int ob = __shfl_sync(0xffffffffu, s0, j + 1);
            int oc = __shfl_sync(0xffffffffu, s0, j + 2);
            int od = __shfl_sync(0xffffffffu, s0, j + 3);
            unsigned ha = *(const unsigned*)(ylane + (size_t)(unsigned)oa);
            unsigned hb = *(const unsigned*)(ylane + (size_t)(unsigned)ob);
            unsigned hc = *(const unsigned*)(ylane + (size_t)(unsigned)oc);
            unsigned hd = *(const unsigned*)(ylane + (size_t)(unsigned)od);
            acc0 = __hadd2(acc0, __hadd2(*(const __half2*)&ha, *(const __half2*)&hb));
            acc1 = __hadd2(acc1, __hadd2(*(const __half2*)&hc, *(const __half2*)&hd));
        }
        for (; j < c0; j++) {
            int oa = __shfl_sync(0xffffffffu, s0, j);
            unsigned ha = *(const unsigned*)(ylane + (size_t)(unsigned)oa);
            acc0 = __hadd2(acc0, *(const __half2*)&ha);
        }
        for (j = 32; j < cnt; j++) {
            int oa = __shfl_sync(0xffffffffu, s1, j - 32);
            unsigned ha = *(const unsigned*)(ylane + (size_t)(unsigned)oa);
            acc1 = __hadd2(acc1, *(const __half2*)&ha);
        }

        float2 f = __half22float2(__hadd2(acc0, acc1));
        float wv = __ldg(&wts[i]);
        float z0 = fmaxf(f.x + b.x, 0.f);
        float z1 = fmaxf(f.y + b.y, 0.f);
        accS.x = fmaf(wv, z0, accS.x);
        accS.y = fmaf(wv, z1, accS.y);
        if (lane == 0) accw += wv;
    }

    // ---- block reduction of partial S ----
    __shared__ float sS[DIM];
    __shared__ float sw;
    __shared__ float sP[256];
    if (threadIdx.x < DIM) sS[threadIdx.x] = 0.f;
    if (threadIdx.x == 0) sw = 0.f;
    __syncthreads();
    atomicAdd(&sS[lane * 2 + 0], accS.x);
    atomicAdd(&sS[lane * 2 + 1], accS.y);
    if (lane == 0) atomicAdd(&sw, accw);
    __syncthreads();

    // ---- apply W2 to block partial: out += sS @ W2 + sw * b2 ----
    {
        int jj = threadIdx.x & 63;
        int kq = threadIdx.x >> 6;
        float acc = 0.f;
        #pragma unroll
        for (int q = 0; q < 16; q++) {
            int k = kq * 16 + q;
            acc = fmaf(sS[k], __ldg(&W2[k * DIM + jj]), acc);
        }
        if (kq == 0) acc = fmaf(sw, __ldg(&b2[jj]), acc);
        sP[threadIdx.x] = acc;
        __syncthreads();
        if (threadIdx.x < DIM)
            atomicAdd(&out[jj], sP[jj] + sP[64 + jj] + sP[128 + jj] + sP[192 + jj]);
    }
}

// ---------------------------------------------------------------------------
extern "C" void kernel_launch(void* const* d_in, const int* in_sizes, int n_in,
                              void* d_out, int out_size) {
    const float* x   = (const float*)d_in[0];
    const void*  ei  = d_in[1];
    const float* wts = (const float*)d_in[2];
    const float* W1  = (const float*)d_in[3];
    const float* b1  = (const float*)d_in[4];
    const float* W2  = (const float*)d_in[5];
    const float* b2  = (const float*)d_in[6];
    float* out = (float*)d_out;

    zero_kernel<<<99, 256>>>(out, W1);
    fused_gemm_bucket_kernel<<<FUSED_BLOCKS, 256>>>(x, ei);
    gather_reduce_kernel<<<GATHER_BLOCKS, 256>>>(wts, b1, W2, b2, out);
}

// round 16
// speedup vs baseline: 3.1101x; 1.0661x over previous
#include <cuda_runtime.h>
#include <cuda_fp16.h>
#include <cstdint>

#define N_NODES 100000
#define DIM 64
#define N_EDGES 1600000
#define MAXDEG 64
#define GATHER_BLOCKS 1184

#define GEMM_BLOCKS ((N_NODES + 127) / 128)        // 782
#define BUCKET_BLOCKS ((N_EDGES + 255) / 256)      // 6250
#define FUSED_BLOCKS (GEMM_BLOCKS + BUCKET_BLOCKS) // 7032

// Scratch (__device__ globals; zero-initialized at load).
__device__ uint4  g_y_h4[(size_t)N_NODES * DIM / 8];  // y = x@W1, fp16 rows (128B)
__device__ int    g_cnt[N_NODES];                     // per-dst degree
__device__ int    g_slots[(size_t)N_NODES * MAXDEG];  // BYTE offsets (src<<7) per dst
__device__ __half g_w1t[DIM * DIM];                   // W1 transposed, fp16: [n][k]

// ---------------------------------------------------------------------------
// Kernel 0: zero g_cnt + out[64]; block 98 builds g_w1t[n][k] = W1[k][n]
// via a SMEM transpose.  Row pad = 8 halves (stride 144B, multiple of 16) so
// the uint4 reads are 16B-aligned — the R15 bug was pad=1 (130B rows).
// ---------------------------------------------------------------------------
__global__ void zero_kernel(float* __restrict__ out, const float* __restrict__ W1) {
    if (blockIdx.x == 98) {
        __shared__ __half sm[DIM][DIM + 8];
        int t = threadIdx.x;
        #pragma unroll
        for (int p = 0; p < 16; p++) {
            int idx = t + 256 * p;              // coalesced read of W1
            int k = idx >> 6, n = idx & 63;
            sm[n][k] = __float2half_rn(W1[idx]);
        }
        __syncthreads();
        // write 16 consecutive halves per thread: g_w1t[t*16 .. t*16+16)
        int base = t * 16;
        int n = base >> 6, k = base & 63;       // k in {0,16,32,48} -> 16B aligned
        uint4 v0 = *(uint4*)&sm[n][k];
        uint4 v1 = *(uint4*)&sm[n][k + 8];
        *(uint4*)&g_w1t[base] = v0;
        *(uint4*)&g_w1t[base + 8] = v1;
        return;
    }
    int i = blockIdx.x * 256 + threadIdx.x;
    if (i < N_NODES / 4) ((uint4*)g_cnt)[i] = make_uint4(0, 0, 0, 0);
    if (i < DIM) out[i] = 0.0f;
}

// ---------------------------------------------------------------------------
// Kernel 1 (fused grid-union; R14-exact): blocks [0,GEMM_BLOCKS) = HMMA gemm
// with wavefront-clean staging; blocks [GEMM_BLOCKS,FUSED_BLOCKS) = bucket.
// ---------------------------------------------------------------------------
__global__ void __launch_bounds__(256) fused_gemm_bucket_kernel(
        const float* __restrict__ x, const void* __restrict__ eptr) {
    int bid = blockIdx.x;
    int t = threadIdx.x;

    if (bid < GEMM_BLOCKS) {
        // ================= GEMM branch =================
        __shared__ __half xs[128][72];
        __shared__ __half wt[64][72];

        // ---- stage W1t: 8KB coalesced (2 x uint4 per thread) ----
        {
            const uint4* src = (const uint4*)g_w1t;     // 512 uint4
            #pragma unroll
            for (int p = 0; p < 2; p++) {
                int idx = t + p * 256;
                uint4 v = src[idx];                     // 8 halfs, row n=idx>>3
                *(uint4*)&wt[idx >> 3][(idx & 7) * 8] = v;
            }
        }

        // ---- stage x tile: LINEAR read of the contiguous 32KB tile ----
        int m0 = bid * 128;
        {
            const char* xb = (const char*)x;
            size_t tile_byte = (size_t)m0 * 256;
            size_t xlimit = (size_t)N_NODES * 256;
            #pragma unroll
            for (int p = 0; p < 8; p++) {
                int off = t * 16 + p * 4096;            // byte within tile
                float4 v = make_float4(0.f, 0.f, 0.f, 0.f);
                if (tile_byte + off < xlimit)
                    v = *(const float4*)(xb + tile_byte + off);
                int row = off >> 8;                     // 256B per x row
                int colh = (off & 255) >> 2;            // half-col index
                *(__half2*)&xs[row][colh]     = __floats2half2_rn(v.x, v.y);
                *(__half2*)&xs[row][colh + 2] = __floats2half2_rn(v.z, v.w);
            }
        }
        __syncthreads();

        // ---- mma mainloop ----
        int w = t >> 5, lane = t & 31;
        int r = lane >> 2, c = lane & 3;
        int mrow = 16 * w + r;

        float C[8][4];
        #pragma unroll
        for (int nt = 0; nt < 8; nt++)
            #pragma unroll
            for (int q = 0; q < 4; q++) C[nt][q] = 0.f;

        #pragma unroll
        for (int ks = 0; ks < 4; ks++) {
            int k0 = ks * 16;
            unsigned a0 = *(const unsigned*)&xs[mrow][k0 + c * 2];
            unsigned a1 = *(const unsigned*)&xs[mrow + 8][k0 + c * 2];
            unsigned a2 = *(const unsigned*)&xs[mrow][k0 + c * 2 + 8];
            unsigned a3 = *(const unsigned*)&xs[mrow + 8][k0 + c * 2 + 8];
            #pragma unroll
            for (int nt = 0; nt < 8; nt++) {
                unsigned b0 = *(const unsigned*)&wt[nt * 8 + r][k0 + c * 2];
                unsigned b1 = *(const unsigned*)&wt[nt * 8 + r][k0 + c * 2 + 8];
                asm("mma.sync.aligned.m16n8k16.row.col.f32.f16.f16.f32 "
                    "{%0,%1,%2,%3}, {%4,%5,%6,%7}, {%8,%9}, {%0,%1,%2,%3};"
                    : "+f"(C[nt][0]), "+f"(C[nt][1]), "+f"(C[nt][2]), "+f"(C[nt][3])
                    : "r"(a0), "r"(a1), "r"(a2), "r"(a3), "r"(b0), "r"(b1));
            }
        }

        // ---- C -> smem (conflict-free STS), then LINEAR coalesced STG ----
        __syncthreads();                    // xs reads done; reuse as C tile
        #pragma unroll
        for (int nt = 0; nt < 8; nt++) {
            int coln = nt * 8 + c * 2;
            *(__half2*)&xs[mrow][coln]     = __floats2half2_rn(C[nt][0], C[nt][1]);
            *(__half2*)&xs[mrow + 8][coln] = __floats2half2_rn(C[nt][2], C[nt][3]);
        }
        __syncthreads();
        {
            char* yb = (char*)g_y_h4;
            size_t ybyte0 = (size_t)m0 * 128;
            size_t ylimit = (size_t)N_NODES * 128;
            #pragma unroll
            for (int p = 0; p < 4; p++) {
                int off = t * 16 + p * 4096;            // byte within y tile
                int row = off >> 7;                     // 128B per y row
                int colh = (off & 127) >> 1;            // half-col index
                uint4 v = *(uint4*)&xs[row][colh];
                if (ybyte0 + off < ylimit)
                    *(uint4*)(yb + ybyte0 + off) = v;
            }
        }
    } else {
        // ================= Bucket branch (lean) =================
        const unsigned* w = (const unsigned*)eptr;
        unsigned o = w[1] | w[3] | w[5] | w[7] | w[9] | w[11] | w[13] | w[15];
        bool is64 = (o == 0);   // int64 little-endian: odd words = zero high halves

        int e = (bid - GEMM_BLOCKS) * 256 + t;
        if (e >= N_EDGES) return;
        int s, d;
        if (is64) {
            const long long* ei = (const long long*)eptr;
            s = (int)__ldg(&ei[e]);
            d = (int)__ldg(&ei[N_EDGES + e]);
        } else {
            const int* ei = (const int*)eptr;
            s = __ldg(&ei[e]);
            d = __ldg(&ei[N_EDGES + e]);
        }
        int pos = atomicAdd(&g_cnt[d], 1);
        if (pos < MAXDEG) g_slots[(size_t)d * MAXDEG + pos] = s << 7;  // byte offset
    }
}

// ---------------------------------------------------------------------------
// Kernel 2: fused gather + epilogue + per-block W2 GEMV into out (R13-exact).
// ---------------------------------------------------------------------------
__global__ void __launch_bounds__(256) gather_reduce_kernel(
        const float* __restrict__ wts, const float* __restrict__ b1,
        const float* __restrict__ W2, const float* __restrict__ b2,
        float* __restrict__ out) {
    int lane = threadIdx.x & 31;
    int warp = threadIdx.x >> 5;
    float2 b = ((const float2*)b1)[lane];

    const char* ylane = (const char*)g_y_h4 + lane * 4;  // per-lane column base

    float2 accS = make_float2(0.f, 0.f);
    float accw = 0.f;

    int gw = blockIdx.x * 8 + warp;
    int nw = GATHER_BLOCKS * 8;
    for (int i = gw; i < N_NODES; i += nw) {
        int cnt = g_cnt[i];
        if (cnt > MAXDEG) cnt = MAXDEG;
        const int* slots = g_slots + (size_t)i * MAXDEG;
        int s0 = (lane < cnt) ? __ldg(&slots[lane]) : 0;
        int s1 = (lane + 32 < cnt) ? __ldg(&slots[lane + 32]) : 0;

        unsigned hs = *(const unsigned*)(ylane + ((size_t)(unsigned)i << 7));
        __half2 acc0 = *(const __half2*)&hs;
        __half2 acc1 = __half2half2(__ushort_as_half(0));

        int c0 = cnt < 32 ? cnt : 32;
        int j = 0;
        for (; j + 4 <= c0; j += 4) {
            int oa = __shfl_sync(0xffffffffu, s0, j + 0);
            int ob = __shfl_sync(0xffffffffu, s0, j + 1);
            int oc = __shfl_sync(0xffffffffu, s0, j + 2);
            int od = __shfl_sync(0xffffffffu, s0, j + 3);
            unsigned ha = *(const unsigned*)(ylane + (size_t)(unsigned)oa);
            unsigned hb = *(const unsigned*)(ylane + (size_t)(unsigned)ob);
            unsigned hc = *(const unsigned*)(ylane + (size_t)(unsigned)oc);
            unsigned hd = *(const unsigned*)(ylane + (size_t)(unsigned)od);
            acc0 = __hadd2(acc0, __hadd2(*(const __half2*)&ha, *(const __half2*)&hb));
            acc1 = __hadd2(acc1, __hadd2(*(const __half2*)&hc, *(const __half2*)&hd));
        }
        for (; j < c0; j++) {
            int oa = __shfl_sync(0xffffffffu, s0, j);
            unsigned ha = *(const unsigned*)(ylane + (size_t)(unsigned)oa);
            acc0 = __hadd2(acc0, *(const __half2*)&ha);
        }
        for (j = 32; j < cnt; j++) {
            int oa = __shfl_sync(0xffffffffu, s1, j - 32);
            unsigned ha = *(const unsigned*)(ylane + (size_t)(unsigned)oa);
            acc1 = __hadd2(acc1, *(const __half2*)&ha);
        }

        float2 f = __half22float2(__hadd2(acc0, acc1));
        float wv = __ldg(&wts[i]);
        float z0 = fmaxf(f.x + b.x, 0.f);
        float z1 = fmaxf(f.y + b.y, 0.f);
        accS.x = fmaf(wv, z0, accS.x);
        accS.y = fmaf(wv, z1, accS.y);
        if (lane == 0) accw += wv;
    }

    // ---- block reduction of partial S ----
    __shared__ float sS[DIM];
    __shared__ float sw;
    __shared__ float sP[256];
    if (threadIdx.x < DIM) sS[threadIdx.x] = 0.f;
    if (threadIdx.x == 0) sw = 0.f;
    __syncthreads();
    atomicAdd(&sS[lane * 2 + 0], accS.x);
    atomicAdd(&sS[lane * 2 + 1], accS.y);
    if (lane == 0) atomicAdd(&sw, accw);
    __syncthreads();

    // ---- apply W2 to block partial: out += sS @ W2 + sw * b2 ----
    {
        int jj = threadIdx.x & 63;
        int kq = threadIdx.x >> 6;
        float acc = 0.f;
        #pragma unroll
        for (int q = 0; q < 16; q++) {
            int k = kq * 16 + q;
            acc = fmaf(sS[k], __ldg(&W2[k * DIM + jj]), acc);
        }
        if (kq == 0) acc = fmaf(sw, __ldg(&b2[jj]), acc);
        sP[threadIdx.x] = acc;
        __syncthreads();
        if (threadIdx.x < DIM)
            atomicAdd(&out[jj], sP[jj] + sP[64 + jj] + sP[128 + jj] + sP[192 + jj]);
    }
}

// ---------------------------------------------------------------------------
extern "C" void kernel_launch(void* const* d_in, const int* in_sizes, int n_in,
                              void* d_out, int out_size) {
    const float* x   = (const float*)d_in[0];
    const void*  ei  = d_in[1];
    const float* wts = (const float*)d_in[2];
    const float* W1  = (const float*)d_in[3];
    const float* b1  = (const float*)d_in[4];
    const float* W2  = (const float*)d_in[5];
    const float* b2  = (const float*)d_in[6];
    float* out = (float*)d_out;

    zero_kernel<<<99, 256>>>(out, W1);
    fused_gemm_bucket_kernel<<<FUSED_BLOCKS, 256>>>(x, ei);
    gather_reduce_kernel<<<GATHER_BLOCKS, 256>>>(wts, b1, W2, b2, out);
}